// round 4
// baseline (speedup 1.0000x reference)
#include <cuda_runtime.h>
#include <cuda_fp16.h>
#include <math.h>

#define NB   4
#define CC   256
#define HH   128
#define WW   128
#define NPIX (HH*WW)            // 16384
#define NPIX_TOT (NB*NPIX)      // 65536
#define NPTS 5
#define G    4                  // channels per CTA, interleaved half4 in smem (128 KB)
#define CG   (CC / G)           // 64 channel-groups per batch
#define SCALE 0.125f

static __device__ __forceinline__ unsigned pack_h2(float a, float b) {
    half2 h = __floats2half2_rn(a, b);
    return *reinterpret_cast<unsigned*>(&h);
}
static __device__ __forceinline__ float2 unpack_h2(unsigned u) {
    half2 h = *reinterpret_cast<half2*>(&u);
    return __half22float2(h);
}

// Packed per-(n,h,w,point) table: x = y_low*W+x_low (or -1 invalid), y = half2(lx, ly)
__device__ int2 g_tab[NPTS][NPIX_TOT];

__global__ void FR_precompute_kernel(const float* __restrict__ bb) {
    int i = blockIdx.x * blockDim.x + threadIdx.x;
    if (i >= NPIX_TOT) return;
    const float* b = bb + (size_t)i * 5;
    float cx = b[0], cy = b[1], w = b[2], h = b[3], t = b[4];
    float st, ct;
    sincosf(t, &st, &ct);
    float vx =  w * ct * 0.5f, vy = w * st * 0.5f;
    float wx = -h * st * 0.5f, wy = h * ct * 0.5f;

    float pxs[NPTS] = {cx, cx + vx + wx, cx - vx + wx, cx - vx - wx, cx + vx - wx};
    float pys[NPTS] = {cy, cy + vy + wy, cy - vy + wy, cy - vy - wy, cy + vy - wy};

#pragma unroll
    for (int p = 0; p < NPTS; p++) {
        float x = pxs[p] * SCALE;
        float y = pys[p] * SCALE;
        bool valid = (y >= -1.0f) && (y <= (float)HH) && (x >= -1.0f) && (x <= (float)WW);
        y = fmaxf(y, 0.0f);
        x = fmaxf(x, 0.0f);
        int yl = min((int)floorf(y), HH - 1);
        int xl = min((int)floorf(x), WW - 1);
        if (yl >= HH - 1) y = (float)yl;   // mmcv border rule
        if (xl >= WW - 1) x = (float)xl;
        float ly = y - (float)yl;
        float lx = x - (float)xl;
        int off = yl * WW + xl;
        int2 e;
        e.x = valid ? off : -1;
        e.y = (int)pack_h2(lx, ly);
        g_tab[p][i] = e;
    }
}

struct Gath { int o00, o01, o10, o11; float w00, w01, w10, w11; };

static __device__ __forceinline__ Gath decode(int2 t) {
    Gath g;
    float vf = (t.x >= 0) ? 1.0f : 0.0f;
    int off = max(t.x, 0);
    float2 l = unpack_h2((unsigned)t.y);
    int xl = off & (WW - 1);
    int yl = off >> 7;
    int dx  = (xl < WW - 1) ? 1  : 0;
    int dyw = (yl < HH - 1) ? WW : 0;
    float hx = 1.0f - l.x, hy = 1.0f - l.y;
    g.w00 = vf * hy * hx;
    g.w01 = vf * hy * l.x;
    g.w10 = vf * l.y * hx;
    g.w11 = vf * l.y * l.x;
    g.o00 = off; g.o01 = off + dx; g.o10 = off + dyw; g.o11 = off + dyw + dx;
    return g;
}

static __device__ __forceinline__ void acc4(float& a0, float& a1, float& a2, float& a3,
                                            uint2 v, float w) {
    float2 c01 = unpack_h2(v.x);
    float2 c23 = unpack_h2(v.y);
    a0 += w * c01.x; a1 += w * c01.y; a2 += w * c23.x; a3 += w * c23.y;
}

// One CTA per (batch, quad of channels). 4 channels interleaved as packed half4
// per pixel in smem; each gather = one LDS.64 serving 4 channels. Two pixels
// per thread iteration for MLP.
__global__ __launch_bounds__(1024, 1)
void FR_refine_kernel(const float* __restrict__ feat, float* __restrict__ out) {
    extern __shared__ unsigned int smem_raw[];
    uint2* sq = (uint2*)smem_raw;              // [NPIX] x packed half4

    int bx = blockIdx.x;
    int n  = bx / CG;
    int c0 = (bx % CG) * G;
    const float* f0 = feat + ((size_t)n * CC + c0) * NPIX;

    for (int p = threadIdx.x; p < NPIX; p += 1024) {
        uint2 pk;
        pk.x = pack_h2(f0[p],          f0[p + NPIX]);
        pk.y = pack_h2(f0[p + 2*NPIX], f0[p + 3*NPIX]);
        sq[p] = pk;
    }
    __syncthreads();

    int tbase = n * NPIX;
    float* ob = out + ((size_t)n * CC + c0) * NPIX;

    for (int it = 0; it < NPIX; it += 2048) {
        int pA = threadIdx.x + it;
        int pB = pA + 1024;

        // residual from smem (fp16 identity term; error ~1.4e-4, within budget)
        uint2 rA = sq[pA];
        uint2 rB = sq[pB];
        float2 tA01 = unpack_h2(rA.x), tA23 = unpack_h2(rA.y);
        float2 tB01 = unpack_h2(rB.x), tB23 = unpack_h2(rB.y);
        float aA0 = tA01.x, aA1 = tA01.y, aA2 = tA23.x, aA3 = tA23.y;
        float aB0 = tB01.x, aB1 = tB01.y, aB2 = tB23.x, aB3 = tB23.y;

#pragma unroll
        for (int p = 0; p < NPTS; p++) {
            int2 eA = g_tab[p][tbase + pA];
            int2 eB = g_tab[p][tbase + pB];
            Gath gA = decode(eA);
            Gath gB = decode(eB);

            uint2 vA0 = sq[gA.o00];
            uint2 vA1 = sq[gA.o01];
            uint2 vA2 = sq[gA.o10];
            uint2 vA3 = sq[gA.o11];
            uint2 vB0 = sq[gB.o00];
            uint2 vB1 = sq[gB.o01];
            uint2 vB2 = sq[gB.o10];
            uint2 vB3 = sq[gB.o11];

            acc4(aA0, aA1, aA2, aA3, vA0, gA.w00);
            acc4(aA0, aA1, aA2, aA3, vA1, gA.w01);
            acc4(aA0, aA1, aA2, aA3, vA2, gA.w10);
            acc4(aA0, aA1, aA2, aA3, vA3, gA.w11);
            acc4(aB0, aB1, aB2, aB3, vB0, gB.w00);
            acc4(aB0, aB1, aB2, aB3, vB1, gB.w01);
            acc4(aB0, aB1, aB2, aB3, vB2, gB.w10);
            acc4(aB0, aB1, aB2, aB3, vB3, gB.w11);
        }

        ob[pA]            = aA0;
        ob[pA + NPIX]     = aA1;
        ob[pA + 2*NPIX]   = aA2;
        ob[pA + 3*NPIX]   = aA3;
        ob[pB]            = aB0;
        ob[pB + NPIX]     = aB1;
        ob[pB + 2*NPIX]   = aB2;
        ob[pB + 3*NPIX]   = aB3;
    }
}

extern "C" void kernel_launch(void* const* d_in, const int* in_sizes, int n_in,
                              void* d_out, int out_size) {
    const float* feat = (const float*)d_in[0];  // [4,256,128,128] f32
    const float* bb   = (const float*)d_in[1];  // [4,128,128,5]   f32
    float*       out  = (float*)d_out;          // [4,256,128,128] f32

    FR_precompute_kernel<<<(NPIX_TOT + 255) / 256, 256>>>(bb);

    size_t smem = (size_t)NPIX * 8;   // 131072 B
    cudaFuncSetAttribute(FR_refine_kernel,
                         cudaFuncAttributeMaxDynamicSharedMemorySize, (int)smem);
    FR_refine_kernel<<<NB * CG, 1024, smem>>>(feat, out);
}

// round 5
// speedup vs baseline: 1.0009x; 1.0009x over previous
#include <cuda_runtime.h>
#include <cuda_fp16.h>
#include <math.h>

#define NB   4
#define CC   256
#define HH   128
#define WW   128
#define NPIX (HH*WW)            // 16384
#define NPIX_TOT (NB*NPIX)      // 65536
#define NPTS 5
#define G    4                  // channels per CTA, interleaved half4 in smem (128 KB)
#define CG   (CC / G)           // 64 channel-groups per batch
#define SCALE 0.125f

static __device__ __forceinline__ unsigned pack_h2(float a, float b) {
    half2 h = __floats2half2_rn(a, b);
    return *reinterpret_cast<unsigned*>(&h);
}
static __device__ __forceinline__ float2 unpack_h2(unsigned u) {
    half2 h = *reinterpret_cast<half2*>(&u);
    return __half22float2(h);
}

// Packed per-(n,h,w,point) table: x = y_low*W+x_low (or -1 invalid), y = half2(lx, ly)
__device__ int2 g_tab[NPTS][NPIX_TOT];

__global__ void FR_precompute_kernel(const float* __restrict__ bb) {
    int i = blockIdx.x * blockDim.x + threadIdx.x;
    if (i >= NPIX_TOT) return;
    const float* b = bb + (size_t)i * 5;
    float cx = b[0], cy = b[1], w = b[2], h = b[3], t = b[4];
    float st, ct;
    sincosf(t, &st, &ct);
    float vx =  w * ct * 0.5f, vy = w * st * 0.5f;
    float wx = -h * st * 0.5f, wy = h * ct * 0.5f;

    float pxs[NPTS] = {cx, cx + vx + wx, cx - vx + wx, cx - vx - wx, cx + vx - wx};
    float pys[NPTS] = {cy, cy + vy + wy, cy - vy + wy, cy - vy - wy, cy + vy - wy};

#pragma unroll
    for (int p = 0; p < NPTS; p++) {
        float x = pxs[p] * SCALE;
        float y = pys[p] * SCALE;
        bool valid = (y >= -1.0f) && (y <= (float)HH) && (x >= -1.0f) && (x <= (float)WW);
        y = fmaxf(y, 0.0f);
        x = fmaxf(x, 0.0f);
        int yl = min((int)floorf(y), HH - 1);
        int xl = min((int)floorf(x), WW - 1);
        if (yl >= HH - 1) y = (float)yl;   // mmcv border rule
        if (xl >= WW - 1) x = (float)xl;
        float ly = y - (float)yl;
        float lx = x - (float)xl;
        int off = yl * WW + xl;
        int2 e;
        e.x = valid ? off : -1;
        e.y = (int)pack_h2(lx, ly);
        g_tab[p][i] = e;
    }
}

// Decode one table entry and accumulate its 4 corner gathers into a0..a3.
static __device__ __forceinline__ void point_acc(const uint2* __restrict__ sq, int2 t,
                                                 float& a0, float& a1, float& a2, float& a3) {
    float vf = (t.x >= 0) ? 1.0f : 0.0f;
    int off = max(t.x, 0);
    float2 l = unpack_h2((unsigned)t.y);
    float lx = l.x, ly = l.y;
    int xl = off & (WW - 1);
    int yl = off >> 7;
    int dx  = (xl < WW - 1) ? 1  : 0;
    int dyw = (yl < HH - 1) ? WW : 0;
    float hx = 1.0f - lx, hy = 1.0f - ly;
    float w00 = vf * hy * hx;
    float w01 = vf * hy * lx;
    float w10 = vf * ly * hx;
    float w11 = vf * ly * lx;

    uint2 v0 = sq[off];
    uint2 v1 = sq[off + dx];
    uint2 v2 = sq[off + dyw];
    uint2 v3 = sq[off + dyw + dx];

    float2 c01, c23;
    c01 = unpack_h2(v0.x); c23 = unpack_h2(v0.y);
    a0 += w00 * c01.x; a1 += w00 * c01.y; a2 += w00 * c23.x; a3 += w00 * c23.y;
    c01 = unpack_h2(v1.x); c23 = unpack_h2(v1.y);
    a0 += w01 * c01.x; a1 += w01 * c01.y; a2 += w01 * c23.x; a3 += w01 * c23.y;
    c01 = unpack_h2(v2.x); c23 = unpack_h2(v2.y);
    a0 += w10 * c01.x; a1 += w10 * c01.y; a2 += w10 * c23.x; a3 += w10 * c23.y;
    c01 = unpack_h2(v3.x); c23 = unpack_h2(v3.y);
    a0 += w11 * c01.x; a1 += w11 * c01.y; a2 += w11 * c23.x; a3 += w11 * c23.y;
}

// One CTA per (batch, quad of channels). 4 channels interleaved as packed half4
// per pixel in smem; each gather = one LDS.64 serving 4 channels. Table entries
// register-double-buffered so the ~234cyc L2 LDG latency hides under compute.
__global__ __launch_bounds__(1024, 1)
void FR_refine_kernel(const float* __restrict__ feat, float* __restrict__ out) {
    extern __shared__ unsigned int smem_raw[];
    uint2* sq = (uint2*)smem_raw;              // [NPIX] x packed half4

    int bx = blockIdx.x;
    int n  = bx / CG;
    int c0 = (bx % CG) * G;
    const float* f0 = feat + ((size_t)n * CC + c0) * NPIX;

    for (int p = threadIdx.x; p < NPIX; p += 1024) {
        uint2 pk;
        pk.x = pack_h2(f0[p],          f0[p + NPIX]);
        pk.y = pack_h2(f0[p + 2*NPIX], f0[p + 3*NPIX]);
        sq[p] = pk;
    }
    __syncthreads();

    int tbase = n * NPIX;
    float* ob = out + ((size_t)n * CC + c0) * NPIX;

    int pix = threadIdx.x;
    // prime the table pipeline
    int2 e0 = g_tab[0][tbase + pix];
    int2 e1 = g_tab[1][tbase + pix];
    int2 e2 = g_tab[2][tbase + pix];
    int2 e3 = g_tab[3][tbase + pix];
    int2 e4 = g_tab[4][tbase + pix];

#pragma unroll 1
    for (int it = 0; it < NPIX / 1024; it++) {
        // prefetch next pixel's table entries (clamped on last iter)
        int pn = tbase + min(pix + 1024, NPIX - 1);
        int2 n0 = g_tab[0][pn];
        int2 n1 = g_tab[1][pn];
        int2 n2 = g_tab[2][pn];
        int2 n3 = g_tab[3][pn];
        int2 n4 = g_tab[4][pn];

        // residual loads for current pixel (fp32, consumed at the bottom)
        float r0 = f0[pix];
        float r1 = f0[pix + NPIX];
        float r2 = f0[pix + 2*NPIX];
        float r3 = f0[pix + 3*NPIX];

        float a0 = 0.f, a1 = 0.f, a2 = 0.f, a3 = 0.f;
        point_acc(sq, e0, a0, a1, a2, a3);
        point_acc(sq, e1, a0, a1, a2, a3);
        point_acc(sq, e2, a0, a1, a2, a3);
        point_acc(sq, e3, a0, a1, a2, a3);
        point_acc(sq, e4, a0, a1, a2, a3);

        ob[pix]            = a0 + r0;
        ob[pix + NPIX]     = a1 + r1;
        ob[pix + 2*NPIX]   = a2 + r2;
        ob[pix + 3*NPIX]   = a3 + r3;

        pix += 1024;
        e0 = n0; e1 = n1; e2 = n2; e3 = n3; e4 = n4;
    }
}

extern "C" void kernel_launch(void* const* d_in, const int* in_sizes, int n_in,
                              void* d_out, int out_size) {
    const float* feat = (const float*)d_in[0];  // [4,256,128,128] f32
    const float* bb   = (const float*)d_in[1];  // [4,128,128,5]   f32
    float*       out  = (float*)d_out;          // [4,256,128,128] f32

    FR_precompute_kernel<<<(NPIX_TOT + 255) / 256, 256>>>(bb);

    size_t smem = (size_t)NPIX * 8;   // 131072 B
    cudaFuncSetAttribute(FR_refine_kernel,
                         cudaFuncAttributeMaxDynamicSharedMemorySize, (int)smem);
    FR_refine_kernel<<<NB * CG, 1024, smem>>>(feat, out);
}

// round 7
// speedup vs baseline: 1.1124x; 1.1113x over previous
#include <cuda_runtime.h>
#include <cuda_fp16.h>
#include <math.h>

#define NB   4
#define CC   256
#define HH   128
#define WW   128
#define NPIX (HH*WW)            // 16384
#define NPIX_TOT (NB*NPIX)      // 65536
#define NPTS 5
#define G    4                  // channels per CTA, interleaved half4 in smem (128 KB)
#define CG   (CC / G)           // 64 channel-groups per batch
#define SCALE 0.125f

static __device__ __forceinline__ unsigned pack_h2(float a, float b) {
    half2 h = __floats2half2_rn(a, b);
    return *reinterpret_cast<unsigned*>(&h);
}
static __device__ __forceinline__ float2 unpack_h2(unsigned u) {
    half2 h = *reinterpret_cast<half2*>(&u);
    return __half22float2(h);
}

// Packed per-(n,h,w,point) table: x = y_low*W+x_low (or -1 invalid), y = half2(lx, ly)
__device__ int2 g_tab[NPTS][NPIX_TOT];

__global__ void FR_precompute_kernel(const float* __restrict__ bb) {
    int i = blockIdx.x * blockDim.x + threadIdx.x;
    if (i >= NPIX_TOT) return;
    const float* b = bb + (size_t)i * 5;
    float cx = b[0], cy = b[1], w = b[2], h = b[3], t = b[4];
    float st, ct;
    sincosf(t, &st, &ct);
    float vx =  w * ct * 0.5f, vy = w * st * 0.5f;
    float wx = -h * st * 0.5f, wy = h * ct * 0.5f;

    float pxs[NPTS] = {cx, cx + vx + wx, cx - vx + wx, cx - vx - wx, cx + vx - wx};
    float pys[NPTS] = {cy, cy + vy + wy, cy - vy + wy, cy - vy - wy, cy + vy - wy};

#pragma unroll
    for (int p = 0; p < NPTS; p++) {
        float x = pxs[p] * SCALE;
        float y = pys[p] * SCALE;
        bool valid = (y >= -1.0f) && (y <= (float)HH) && (x >= -1.0f) && (x <= (float)WW);
        y = fmaxf(y, 0.0f);
        x = fmaxf(x, 0.0f);
        int yl = min((int)floorf(y), HH - 1);
        int xl = min((int)floorf(x), WW - 1);
        if (yl >= HH - 1) y = (float)yl;   // mmcv border rule
        if (xl >= WW - 1) x = (float)xl;
        float ly = y - (float)yl;
        float lx = x - (float)xl;
        int off = yl * WW + xl;
        int2 e;
        e.x = valid ? off : -1;
        e.y = (int)pack_h2(lx, ly);
        g_tab[p][i] = e;
    }
}

// Decode one table entry: 4 smem offsets + 4 weights packed as two half2.
// Packed weights keep the register footprint at 2 regs/point for all weights.
static __device__ __forceinline__ void decode_pt(int2 t, int o[4], unsigned wpk[2]) {
    float vf = (t.x >= 0) ? 1.0f : 0.0f;
    int off = max(t.x, 0);
    float2 l = unpack_h2((unsigned)t.y);
    float lx = l.x, ly = l.y;
    int xl = off & (WW - 1);
    int yl = off >> 7;
    int dx  = (xl < WW - 1) ? 1  : 0;
    int dyw = (yl < HH - 1) ? WW : 0;
    float hx = 1.0f - lx, hy = 1.0f - ly;
    wpk[0] = pack_h2(vf * hy * hx, vf * hy * lx);   // w00, w01
    wpk[1] = pack_h2(vf * ly * hx, vf * ly * lx);   // w10, w11
    o[0] = off; o[1] = off + dx; o[2] = off + dyw; o[3] = off + dyw + dx;
}

static __device__ __forceinline__ void fma_corner(float& a0, float& a1, float& a2, float& a3,
                                                  uint2 v, float w) {
    float2 c01 = unpack_h2(v.x);
    float2 c23 = unpack_h2(v.y);
    a0 += w * c01.x; a1 += w * c01.y; a2 += w * c23.x; a3 += w * c23.y;
}

static __device__ __forceinline__ void fma_pt(float& a0, float& a1, float& a2, float& a3,
                                              const uint2 v[4], const unsigned wpk[2]) {
    float2 wa = unpack_h2(wpk[0]);
    float2 wb = unpack_h2(wpk[1]);
    fma_corner(a0, a1, a2, a3, v[0], wa.x);
    fma_corner(a0, a1, a2, a3, v[1], wa.y);
    fma_corner(a0, a1, a2, a3, v[2], wb.x);
    fma_corner(a0, a1, a2, a3, v[3], wb.y);
}

// One CTA per (batch, quad of channels). 4 channels interleaved as packed half4
// per pixel in smem; each gather = one LDS.64 serving 4 channels. Points are
// software-pipelined in groups (3 pts = 12 LDS, then 2 pts = 8 LDS) so 12-20
// independent LDS are in flight before any dependent FMA executes.
__global__ __launch_bounds__(1024, 1)
void FR_refine_kernel(const float* __restrict__ feat, float* __restrict__ out) {
    extern __shared__ unsigned int smem_raw[];
    uint2* sq = (uint2*)smem_raw;              // [NPIX] x packed half4

    int bx = blockIdx.x;
    int n  = bx / CG;
    int c0 = (bx % CG) * G;
    const float* f0 = feat + ((size_t)n * CC + c0) * NPIX;

    // Vectorized fill: float4 per plane per lane.
    {
        const float4* s0 = (const float4*)f0;
        const float4* s1 = (const float4*)(f0 + NPIX);
        const float4* s2 = (const float4*)(f0 + 2*NPIX);
        const float4* s3 = (const float4*)(f0 + 3*NPIX);
        for (int q = threadIdx.x; q < NPIX/4; q += 1024) {
            float4 a = s0[q], b = s1[q], c = s2[q], d = s3[q];
            sq[4*q+0] = make_uint2(pack_h2(a.x, b.x), pack_h2(c.x, d.x));
            sq[4*q+1] = make_uint2(pack_h2(a.y, b.y), pack_h2(c.y, d.y));
            sq[4*q+2] = make_uint2(pack_h2(a.z, b.z), pack_h2(c.z, d.z));
            sq[4*q+3] = make_uint2(pack_h2(a.w, b.w), pack_h2(c.w, d.w));
        }
    }
    __syncthreads();

    int tbase = n * NPIX;
    float* ob = out + ((size_t)n * CC + c0) * NPIX;

    for (int pix = threadIdx.x; pix < NPIX; pix += 1024) {
        // residual loads issue first (independent, consumed at the very end)
        float r0 = f0[pix];
        float r1 = f0[pix + NPIX];
        float r2 = f0[pix + 2*NPIX];
        float r3 = f0[pix + 3*NPIX];

        int2 e0 = g_tab[0][tbase + pix];
        int2 e1 = g_tab[1][tbase + pix];
        int2 e2 = g_tab[2][tbase + pix];
        int2 e3 = g_tab[3][tbase + pix];
        int2 e4 = g_tab[4][tbase + pix];

        // ---- group 1: points 0-2 -> 12 LDS in flight
        int oA[4], oB[4], oC[4];
        unsigned wA[2], wB[2], wC[2];
        decode_pt(e0, oA, wA);
        decode_pt(e1, oB, wB);
        decode_pt(e2, oC, wC);

        uint2 vA[4], vB[4], vC[4];
#pragma unroll
        for (int k = 0; k < 4; k++) vA[k] = sq[oA[k]];
#pragma unroll
        for (int k = 0; k < 4; k++) vB[k] = sq[oB[k]];
#pragma unroll
        for (int k = 0; k < 4; k++) vC[k] = sq[oC[k]];

        // ---- group 2: points 3-4 -> 8 more LDS issued before group-1 FMAs
        int oD[4], oE[4];
        unsigned wD[2], wE[2];
        decode_pt(e3, oD, wD);
        decode_pt(e4, oE, wE);

        uint2 vD[4], vE[4];
#pragma unroll
        for (int k = 0; k < 4; k++) vD[k] = sq[oD[k]];
#pragma unroll
        for (int k = 0; k < 4; k++) vE[k] = sq[oE[k]];

        float a0 = r0, a1 = r1, a2 = r2, a3 = r3;
        fma_pt(a0, a1, a2, a3, vA, wA);
        fma_pt(a0, a1, a2, a3, vB, wB);
        fma_pt(a0, a1, a2, a3, vC, wC);
        fma_pt(a0, a1, a2, a3, vD, wD);
        fma_pt(a0, a1, a2, a3, vE, wE);

        ob[pix]            = a0;
        ob[pix + NPIX]     = a1;
        ob[pix + 2*NPIX]   = a2;
        ob[pix + 3*NPIX]   = a3;
    }
}

extern "C" void kernel_launch(void* const* d_in, const int* in_sizes, int n_in,
                              void* d_out, int out_size) {
    const float* feat = (const float*)d_in[0];  // [4,256,128,128] f32
    const float* bb   = (const float*)d_in[1];  // [4,128,128,5]   f32
    float*       out  = (float*)d_out;          // [4,256,128,128] f32

    FR_precompute_kernel<<<(NPIX_TOT + 255) / 256, 256>>>(bb);

    size_t smem = (size_t)NPIX * 8;   // 131072 B
    cudaFuncSetAttribute(FR_refine_kernel,
                         cudaFuncAttributeMaxDynamicSharedMemorySize, (int)smem);
    FR_refine_kernel<<<NB * CG, 1024, smem>>>(feat, out);
}